// round 9
// baseline (speedup 1.0000x reference)
#include <cuda_runtime.h>
#include <cuda_fp16.h>
#include <cstdint>

// ---------------- problem constants ----------------
#define BATCH   2048
#define NATOM   96
#define NIN     128
#define NHID    64
#define SHIFTC  0.6931471805599453f

// ---------------- precomputed W1 fp16 image (B-fragment layout) ----------------
// uint2 index = (nt*8 + kt)*32 + lane ; .x = b0 (k pair, khalf 0), .y = b1 (khalf 1)
__device__ __align__(16) uint2 g_wh[2048];   // 16 KB, L1/L2-resident

// W1 is [NIN=128][NHID=64] row-major.  B fragment for mma.m16n8k16.row.col:
// lane = g*4+tg holds b0 = W[n=nt*8+g][k=kt*16+2tg+{0,1}], b1 = same n, k+8+{0,1}.
__global__ void prep_w_kernel(const float* __restrict__ W1) {
    int idx = blockIdx.x * blockDim.x + threadIdx.x;
    if (idx >= NIN * NHID) return;
    int k = idx >> 6;          // 0..127
    int n = idx & 63;          // 0..63
    __half h = __float2half_rn(W1[idx]);
    int nt = n >> 3, g = n & 7;
    int kt = k >> 4, kl = k & 15;
    int tg = (kl >> 1) & 3, br = kl >> 3, odd = kl & 1;
    uint32_t off = (uint32_t)((((nt * 8 + kt) * 32 + (g * 4 + tg)) * 8) + br * 4 + odd * 2);
    *reinterpret_cast<__half*>(reinterpret_cast<unsigned char*>(g_wh) + off) = h;
}

// ---------------- device helpers ----------------
__device__ __forceinline__ void mma_f16(float* c, const uint32_t* a, const uint32_t* b) {
    asm volatile(
        "mma.sync.aligned.m16n8k16.row.col.f32.f16.f16.f32 "
        "{%0,%1,%2,%3}, {%4,%5,%6,%7}, {%8,%9}, {%0,%1,%2,%3};"
        : "+f"(c[0]), "+f"(c[1]), "+f"(c[2]), "+f"(c[3])
        : "r"(a[0]), "r"(a[1]), "r"(a[2]), "r"(a[3]), "r"(b[0]), "r"(b[1]));
}

__device__ __forceinline__ float ssp(float z) {
    // shifted softplus, numerically stable
    return fmaxf(z, 0.f) + __logf(1.f + __expf(-fabsf(z))) - SHIFTC;
}

// hi/lo fp16 split of a float2 into packed half2 registers (x = xh + xl to ~2^-22)
__device__ __forceinline__ void split2h(float2 v, uint32_t& hi, uint32_t& lo) {
    __half2 h = __floats2half2_rn(v.x, v.y);
    float rx = v.x - __low2float(h);
    float ry = v.y - __high2float(h);
    __half2 l = __floats2half2_rn(rx, ry);
    hi = *reinterpret_cast<uint32_t*>(&h);
    lo = *reinterpret_cast<uint32_t*>(&l);
}

// ---------------- main fused kernel: one CTA (3 warps) per batch sample ----------------
// Warp w owns atom rows [32w, 32w+32) as TWO m16 tiles.  fp16 2-chain arithmetic:
// x·W = (xh + xl)·Wh.  R8 showed the kernel is DRAM-MLP limited (8 loads in flight
// per warp -> 3.4 TB/s); registers are exactly full so the in-flight window cannot
// grow in-register.  Fix: prologue prefetch.global.L2 of the warp's entire A
// working set (32 rows x 4 lines/thread, no register or scoreboard cost) so demand
// LDGs hit L2 (~250cyc), which the 1-stage register prefetch already covers.
__global__ void __launch_bounds__(96, 4)
atomwise_kernel(const float* __restrict__ rep,
                const int*   __restrict__ atomic_numbers,
                const float* __restrict__ atom_mask,
                const float* __restrict__ b1,
                const float* __restrict__ W2,
                const float* __restrict__ b2,
                const float* __restrict__ atomref,
                const float* __restrict__ mean,
                const float* __restrict__ stddev,
                float*       __restrict__ out) {
    __shared__ float red[4];

    const int tid  = threadIdx.x;
    const int w    = tid >> 5;          // warp 0..2
    const int lane = tid & 31;
    const int b    = blockIdx.x;

    const int qr = lane >> 2;           // 0..7 (row group)
    const int qc = lane & 3;            // 0..3 (col pair)
    const int r0 = w * 32 + qr;         // rows r0, r0+8 (m-tile 0); r0+16, r0+24 (m-tile 1)

    const float* xb = rep + (size_t)b * (NATOM * NIN);

    // ---- L2 prefetch of this warp's whole A slice: 32 rows x 512B = 4 lines/thread ----
    {
        const char* pr = reinterpret_cast<const char*>(xb + (w * 32 + lane) * NIN);
        asm volatile("prefetch.global.L2 [%0];"       :: "l"(pr));
        asm volatile("prefetch.global.L2 [%0+128];"   :: "l"(pr));
        asm volatile("prefetch.global.L2 [%0+256];"   :: "l"(pr));
        asm volatile("prefetch.global.L2 [%0+384];"   :: "l"(pr));
    }

    const float* p0 = xb + (r0     ) * NIN + qc * 2;
    const float* p1 = xb + (r0 +  8) * NIN + qc * 2;
    const float* p2 = xb + (r0 + 16) * NIN + qc * 2;
    const float* p3 = xb + (r0 + 24) * NIN + qc * 2;

    float acc[2][8][4];
    #pragma unroll
    for (int m = 0; m < 2; m++)
        #pragma unroll
        for (int nt = 0; nt < 8; nt++)
            #pragma unroll
            for (int r = 0; r < 4; r++) acc[m][nt][r] = 0.f;

    // prefetch buffer: A fragments for the current kt (8 float2)
    float2 xf[8];
    xf[0] = __ldg(reinterpret_cast<const float2*>(p0));
    xf[1] = __ldg(reinterpret_cast<const float2*>(p1));
    xf[2] = __ldg(reinterpret_cast<const float2*>(p0 + 8));
    xf[3] = __ldg(reinterpret_cast<const float2*>(p1 + 8));
    xf[4] = __ldg(reinterpret_cast<const float2*>(p2));
    xf[5] = __ldg(reinterpret_cast<const float2*>(p3));
    xf[6] = __ldg(reinterpret_cast<const float2*>(p2 + 8));
    xf[7] = __ldg(reinterpret_cast<const float2*>(p3 + 8));

    #pragma unroll
    for (int kt = 0; kt < 8; kt++) {
        // split current A fragments to fp16 hi/lo
        uint32_t ahi0[4], alo0[4], ahi1[4], alo1[4];
        split2h(xf[0], ahi0[0], alo0[0]);
        split2h(xf[1], ahi0[1], alo0[1]);
        split2h(xf[2], ahi0[2], alo0[2]);
        split2h(xf[3], ahi0[3], alo0[3]);
        split2h(xf[4], ahi1[0], alo1[0]);
        split2h(xf[5], ahi1[1], alo1[1]);
        split2h(xf[6], ahi1[2], alo1[2]);
        split2h(xf[7], ahi1[3], alo1[3]);

        // issue next kt's A loads NOW — covered by the MMA block below
        if (kt < 7) {
            int o = (kt + 1) * 16;
            xf[0] = __ldg(reinterpret_cast<const float2*>(p0 + o));
            xf[1] = __ldg(reinterpret_cast<const float2*>(p1 + o));
            xf[2] = __ldg(reinterpret_cast<const float2*>(p0 + o + 8));
            xf[3] = __ldg(reinterpret_cast<const float2*>(p1 + o + 8));
            xf[4] = __ldg(reinterpret_cast<const float2*>(p2 + o));
            xf[5] = __ldg(reinterpret_cast<const float2*>(p3 + o));
            xf[6] = __ldg(reinterpret_cast<const float2*>(p2 + o + 8));
            xf[7] = __ldg(reinterpret_cast<const float2*>(p3 + o + 8));
        }

        #pragma unroll
        for (int nt = 0; nt < 8; nt++) {
            uint2 bb = __ldg(&g_wh[(nt * 8 + kt) * 32 + lane]);  // L1-hit after warmup
            // 2 chains x 2 m-tiles
            mma_f16(acc[0][nt], ahi0, &bb.x);   // xh * Wh
            mma_f16(acc[1][nt], ahi1, &bb.x);
            mma_f16(acc[0][nt], alo0, &bb.x);   // xl * Wh
            mma_f16(acc[1][nt], alo1, &bb.x);
        }
    }

    // ---- epilogue: bias + ssp + W2 dot, quad shuffle-reduce ----
    float sum0 = 0.f, sum1 = 0.f, sum2 = 0.f, sum3 = 0.f;  // rows r0, r0+8, r0+16, r0+24
    const int tg2 = qc * 2;
    #pragma unroll
    for (int nt = 0; nt < 8; nt++) {
        int c0 = nt * 8 + tg2;
        float2 b1v = __ldg(reinterpret_cast<const float2*>(b1 + c0));
        float2 w2v = __ldg(reinterpret_cast<const float2*>(W2 + c0));
        sum0 = fmaf(ssp(acc[0][nt][0] + b1v.x), w2v.x, sum0);
        sum0 = fmaf(ssp(acc[0][nt][1] + b1v.y), w2v.y, sum0);
        sum1 = fmaf(ssp(acc[0][nt][2] + b1v.x), w2v.x, sum1);
        sum1 = fmaf(ssp(acc[0][nt][3] + b1v.y), w2v.y, sum1);
        sum2 = fmaf(ssp(acc[1][nt][0] + b1v.x), w2v.x, sum2);
        sum2 = fmaf(ssp(acc[1][nt][1] + b1v.y), w2v.y, sum2);
        sum3 = fmaf(ssp(acc[1][nt][2] + b1v.x), w2v.x, sum3);
        sum3 = fmaf(ssp(acc[1][nt][3] + b1v.y), w2v.y, sum3);
    }
    // reduce over the 4 lanes of each quad (cols)
    sum0 += __shfl_xor_sync(0xffffffffu, sum0, 1);
    sum0 += __shfl_xor_sync(0xffffffffu, sum0, 2);
    sum1 += __shfl_xor_sync(0xffffffffu, sum1, 1);
    sum1 += __shfl_xor_sync(0xffffffffu, sum1, 2);
    sum2 += __shfl_xor_sync(0xffffffffu, sum2, 1);
    sum2 += __shfl_xor_sync(0xffffffffu, sum2, 2);
    sum3 += __shfl_xor_sync(0xffffffffu, sum3, 1);
    sum3 += __shfl_xor_sync(0xffffffffu, sum3, 2);

    // per-row finish on quad leaders, then warp-sum (deterministic)
    float contrib = 0.f;
    if (qc == 0) {
        float scB2 = b2[0], scMean = mean[0], scStd = stddev[0];
        float s[4] = {sum0, sum1, sum2, sum3};
        float tot = 0.f;
        #pragma unroll
        for (int m = 0; m < 4; m++) {
            int row = r0 + m * 8;
            int g = b * NATOM + row;
            float v = (s[m] + scB2) * scStd + scMean;
            v += atomref[atomic_numbers[g]];
            v *= atom_mask[g];
            tot += v;
        }
        contrib = tot;
    }
    // nonzero only at lanes ≡ 0 (mod 4): stages 4, 8, 16 suffice
    contrib += __shfl_xor_sync(0xffffffffu, contrib, 4);
    contrib += __shfl_xor_sync(0xffffffffu, contrib, 8);
    contrib += __shfl_xor_sync(0xffffffffu, contrib, 16);

    if (lane == 0) red[w] = contrib;
    __syncthreads();
    if (tid == 0) out[b] = red[0] + red[1] + red[2];
}

// ---------------- host launch ----------------
extern "C" void kernel_launch(void* const* d_in, const int* in_sizes, int n_in,
                              void* d_out, int out_size) {
    const float* rep   = (const float*)d_in[0];
    const int*   zn    = (const int*)  d_in[1];
    const float* mask  = (const float*)d_in[2];
    const float* W1    = (const float*)d_in[3];
    const float* b1    = (const float*)d_in[4];
    const float* W2    = (const float*)d_in[5];
    const float* b2    = (const float*)d_in[6];
    const float* aref  = (const float*)d_in[7];
    const float* mean  = (const float*)d_in[8];
    const float* stdd  = (const float*)d_in[9];
    float* out = (float*)d_out;

    prep_w_kernel<<<32, 256>>>(W1);
    atomwise_kernel<<<BATCH, 96>>>(rep, zn, mask, b1, W2, b2, aref, mean, stdd, out);
}

// round 10
// speedup vs baseline: 1.1393x; 1.1393x over previous
#include <cuda_runtime.h>
#include <cuda_fp16.h>
#include <cstdint>

// ---------------- problem constants ----------------
#define BATCH   2048
#define NATOM   96
#define NIN     128
#define NHID    64
#define SHIFTC  0.6931471805599453f

// ---------------- precomputed W1 fp16 image (B-fragment layout) ----------------
// uint2 index = (nt*8 + kt)*32 + lane ; .x = b0 (k pair, khalf 0), .y = b1 (khalf 1)
__device__ __align__(16) uint2 g_wh[2048];   // 16 KB, L1/L2-resident

// W1 is [NIN=128][NHID=64] row-major.  B fragment for mma.m16n8k16.row.col:
// lane = g*4+tg holds b0 = W[n=nt*8+g][k=kt*16+2tg+{0,1}], b1 = same n, k+8+{0,1}.
__global__ void prep_w_kernel(const float* __restrict__ W1) {
    int idx = blockIdx.x * blockDim.x + threadIdx.x;
    if (idx >= NIN * NHID) return;
    int k = idx >> 6;          // 0..127
    int n = idx & 63;          // 0..63
    __half h = __float2half_rn(W1[idx]);
    int nt = n >> 3, g = n & 7;
    int kt = k >> 4, kl = k & 15;
    int tg = (kl >> 1) & 3, br = kl >> 3, odd = kl & 1;
    uint32_t off = (uint32_t)((((nt * 8 + kt) * 32 + (g * 4 + tg)) * 8) + br * 4 + odd * 2);
    *reinterpret_cast<__half*>(reinterpret_cast<unsigned char*>(g_wh) + off) = h;
}

// ---------------- device helpers ----------------
__device__ __forceinline__ void mma_f16(float* c, const uint32_t* a, const uint32_t* b) {
    asm volatile(
        "mma.sync.aligned.m16n8k16.row.col.f32.f16.f16.f32 "
        "{%0,%1,%2,%3}, {%4,%5,%6,%7}, {%8,%9}, {%0,%1,%2,%3};"
        : "+f"(c[0]), "+f"(c[1]), "+f"(c[2]), "+f"(c[3])
        : "r"(a[0]), "r"(a[1]), "r"(a[2]), "r"(a[3]), "r"(b[0]), "r"(b[1]));
}

__device__ __forceinline__ float ssp(float z) {
    // shifted softplus, numerically stable
    return fmaxf(z, 0.f) + __logf(1.f + __expf(-fabsf(z))) - SHIFTC;
}

__device__ __forceinline__ uint32_t cvt2h(float2 v) {
    __half2 h = __floats2half2_rn(v.x, v.y);
    return *reinterpret_cast<uint32_t*>(&h);
}

// ---------------- main fused kernel: one CTA (3 warps) per batch sample ----------------
// Warp w owns atom rows [32w, 32w+32) as TWO m16 tiles.  Single-chain pure fp16:
// R8 measured 9.9e-5 rel_err from quantizing W alone; quantizing x adds the same
// perturbation scale -> ~2e-4 total vs the 1e-3 gate.  Per warp*kt the instruction
// stream drops ~110 -> ~48 (the R9 flat result showed the kernel is issue/critical-
// path bound, so instruction count is the binding resource).  Freed registers
// (no xl fragments) allow 5 CTAs/SM via __launch_bounds__(96,5).
__global__ void __launch_bounds__(96, 5)
atomwise_kernel(const float* __restrict__ rep,
                const int*   __restrict__ atomic_numbers,
                const float* __restrict__ atom_mask,
                const float* __restrict__ b1,
                const float* __restrict__ W2,
                const float* __restrict__ b2,
                const float* __restrict__ atomref,
                const float* __restrict__ mean,
                const float* __restrict__ stddev,
                float*       __restrict__ out) {
    __shared__ float red[4];

    const int tid  = threadIdx.x;
    const int w    = tid >> 5;          // warp 0..2
    const int lane = tid & 31;
    const int b    = blockIdx.x;

    const int qr = lane >> 2;           // 0..7 (row group)
    const int qc = lane & 3;            // 0..3 (col pair)
    const int r0 = w * 32 + qr;         // rows r0, r0+8 (m-tile 0); r0+16, r0+24 (m-tile 1)

    const float* xb = rep + (size_t)b * (NATOM * NIN);

    // ---- L2 prefetch of this warp's whole A slice: 32 rows x 512B = 4 lines/thread ----
    {
        const char* pr = reinterpret_cast<const char*>(xb + (w * 32 + lane) * NIN);
        asm volatile("prefetch.global.L2 [%0];"       :: "l"(pr));
        asm volatile("prefetch.global.L2 [%0+128];"   :: "l"(pr));
        asm volatile("prefetch.global.L2 [%0+256];"   :: "l"(pr));
        asm volatile("prefetch.global.L2 [%0+384];"   :: "l"(pr));
    }

    const float* p0 = xb + (r0     ) * NIN + qc * 2;
    const float* p1 = xb + (r0 +  8) * NIN + qc * 2;
    const float* p2 = xb + (r0 + 16) * NIN + qc * 2;
    const float* p3 = xb + (r0 + 24) * NIN + qc * 2;

    float acc[2][8][4];
    #pragma unroll
    for (int m = 0; m < 2; m++)
        #pragma unroll
        for (int nt = 0; nt < 8; nt++)
            #pragma unroll
            for (int r = 0; r < 4; r++) acc[m][nt][r] = 0.f;

    // prefetch buffer: A fragments for the current kt (8 float2)
    float2 xf[8];
    xf[0] = __ldg(reinterpret_cast<const float2*>(p0));
    xf[1] = __ldg(reinterpret_cast<const float2*>(p1));
    xf[2] = __ldg(reinterpret_cast<const float2*>(p0 + 8));
    xf[3] = __ldg(reinterpret_cast<const float2*>(p1 + 8));
    xf[4] = __ldg(reinterpret_cast<const float2*>(p2));
    xf[5] = __ldg(reinterpret_cast<const float2*>(p3));
    xf[6] = __ldg(reinterpret_cast<const float2*>(p2 + 8));
    xf[7] = __ldg(reinterpret_cast<const float2*>(p3 + 8));

    #pragma unroll
    for (int kt = 0; kt < 8; kt++) {
        // convert current A fragments to fp16 (single chain)
        uint32_t a0[4], a1[4];
        a0[0] = cvt2h(xf[0]);
        a0[1] = cvt2h(xf[1]);
        a0[2] = cvt2h(xf[2]);
        a0[3] = cvt2h(xf[3]);
        a1[0] = cvt2h(xf[4]);
        a1[1] = cvt2h(xf[5]);
        a1[2] = cvt2h(xf[6]);
        a1[3] = cvt2h(xf[7]);

        // issue next kt's A loads NOW — covered by the MMA block below
        if (kt < 7) {
            int o = (kt + 1) * 16;
            xf[0] = __ldg(reinterpret_cast<const float2*>(p0 + o));
            xf[1] = __ldg(reinterpret_cast<const float2*>(p1 + o));
            xf[2] = __ldg(reinterpret_cast<const float2*>(p0 + o + 8));
            xf[3] = __ldg(reinterpret_cast<const float2*>(p1 + o + 8));
            xf[4] = __ldg(reinterpret_cast<const float2*>(p2 + o));
            xf[5] = __ldg(reinterpret_cast<const float2*>(p3 + o));
            xf[6] = __ldg(reinterpret_cast<const float2*>(p2 + o + 8));
            xf[7] = __ldg(reinterpret_cast<const float2*>(p3 + o + 8));
        }

        #pragma unroll
        for (int nt = 0; nt < 8; nt++) {
            uint2 bb = __ldg(&g_wh[(nt * 8 + kt) * 32 + lane]);  // L1-hit after warmup
            mma_f16(acc[0][nt], a0, &bb.x);
            mma_f16(acc[1][nt], a1, &bb.x);
        }
    }

    // ---- epilogue: bias + ssp + W2 dot, quad shuffle-reduce ----
    float sum0 = 0.f, sum1 = 0.f, sum2 = 0.f, sum3 = 0.f;  // rows r0, r0+8, r0+16, r0+24
    const int tg2 = qc * 2;
    #pragma unroll
    for (int nt = 0; nt < 8; nt++) {
        int c0 = nt * 8 + tg2;
        float2 b1v = __ldg(reinterpret_cast<const float2*>(b1 + c0));
        float2 w2v = __ldg(reinterpret_cast<const float2*>(W2 + c0));
        sum0 = fmaf(ssp(acc[0][nt][0] + b1v.x), w2v.x, sum0);
        sum0 = fmaf(ssp(acc[0][nt][1] + b1v.y), w2v.y, sum0);
        sum1 = fmaf(ssp(acc[0][nt][2] + b1v.x), w2v.x, sum1);
        sum1 = fmaf(ssp(acc[0][nt][3] + b1v.y), w2v.y, sum1);
        sum2 = fmaf(ssp(acc[1][nt][0] + b1v.x), w2v.x, sum2);
        sum2 = fmaf(ssp(acc[1][nt][1] + b1v.y), w2v.y, sum2);
        sum3 = fmaf(ssp(acc[1][nt][2] + b1v.x), w2v.x, sum3);
        sum3 = fmaf(ssp(acc[1][nt][3] + b1v.y), w2v.y, sum3);
    }
    // reduce over the 4 lanes of each quad (cols)
    sum0 += __shfl_xor_sync(0xffffffffu, sum0, 1);
    sum0 += __shfl_xor_sync(0xffffffffu, sum0, 2);
    sum1 += __shfl_xor_sync(0xffffffffu, sum1, 1);
    sum1 += __shfl_xor_sync(0xffffffffu, sum1, 2);
    sum2 += __shfl_xor_sync(0xffffffffu, sum2, 1);
    sum2 += __shfl_xor_sync(0xffffffffu, sum2, 2);
    sum3 += __shfl_xor_sync(0xffffffffu, sum3, 1);
    sum3 += __shfl_xor_sync(0xffffffffu, sum3, 2);

    // per-row finish on quad leaders, then warp-sum (deterministic)
    float contrib = 0.f;
    if (qc == 0) {
        float scB2 = b2[0], scMean = mean[0], scStd = stddev[0];
        float s[4] = {sum0, sum1, sum2, sum3};
        float tot = 0.f;
        #pragma unroll
        for (int m = 0; m < 4; m++) {
            int row = r0 + m * 8;
            int g = b * NATOM + row;
            float v = (s[m] + scB2) * scStd + scMean;
            v += atomref[atomic_numbers[g]];
            v *= atom_mask[g];
            tot += v;
        }
        contrib = tot;
    }
    // nonzero only at lanes ≡ 0 (mod 4): stages 4, 8, 16 suffice
    contrib += __shfl_xor_sync(0xffffffffu, contrib, 4);
    contrib += __shfl_xor_sync(0xffffffffu, contrib, 8);
    contrib += __shfl_xor_sync(0xffffffffu, contrib, 16);

    if (lane == 0) red[w] = contrib;
    __syncthreads();
    if (tid == 0) out[b] = red[0] + red[1] + red[2];
}

// ---------------- host launch ----------------
extern "C" void kernel_launch(void* const* d_in, const int* in_sizes, int n_in,
                              void* d_out, int out_size) {
    const float* rep   = (const float*)d_in[0];
    const int*   zn    = (const int*)  d_in[1];
    const float* mask  = (const float*)d_in[2];
    const float* W1    = (const float*)d_in[3];
    const float* b1    = (const float*)d_in[4];
    const float* W2    = (const float*)d_in[5];
    const float* b2    = (const float*)d_in[6];
    const float* aref  = (const float*)d_in[7];
    const float* mean  = (const float*)d_in[8];
    const float* stdd  = (const float*)d_in[9];
    float* out = (float*)d_out;

    prep_w_kernel<<<32, 256>>>(W1);
    atomwise_kernel<<<BATCH, 96>>>(rep, zn, mask, b1, W2, b2, aref, mean, stdd, out);
}

// round 11
// speedup vs baseline: 1.3135x; 1.1530x over previous
#include <cuda_runtime.h>
#include <cuda_fp16.h>
#include <cstdint>

// ---------------- problem constants ----------------
#define BATCH   2048
#define NATOM   96
#define NIN     128
#define NHID    64
#define SHIFTC  0.6931471805599453f

// SMEM A tile: 32 rows/warp, 256B data + 16B pad = 272B stride, bit-4 XOR swizzle.
//  - STS.64 fill: 32 lanes x 8B contiguous per row -> conflict-free
//  - ldmatrix phase reads rows r..r+7 (and r+8.. with XOR'd bit4): start banks
//    (68r + c/4) mod 32 with the XOR giving +-4 on the r+8 half -> 16 distinct.
#define ROWB  272
#define WTILE (32 * ROWB)   // 8704 B per warp

// ---------------- precomputed W1 fp16 image (B-fragment layout) ----------------
// uint2 index = (nt*8 + kt)*32 + lane ; .x = b0 (k pair, khalf 0), .y = b1 (khalf 1)
__device__ __align__(16) uint2 g_wh[2048];   // 16 KB, L1/L2-resident

__global__ void prep_w_kernel(const float* __restrict__ W1) {
    int idx = blockIdx.x * blockDim.x + threadIdx.x;
    if (idx >= NIN * NHID) return;
    int k = idx >> 6;          // 0..127
    int n = idx & 63;          // 0..63
    __half h = __float2half_rn(W1[idx]);
    int nt = n >> 3, g = n & 7;
    int kt = k >> 4, kl = k & 15;
    int tg = (kl >> 1) & 3, br = kl >> 3, odd = kl & 1;
    uint32_t off = (uint32_t)((((nt * 8 + kt) * 32 + (g * 4 + tg)) * 8) + br * 4 + odd * 2);
    *reinterpret_cast<__half*>(reinterpret_cast<unsigned char*>(g_wh) + off) = h;
}

// ---------------- device helpers ----------------
__device__ __forceinline__ void mma_f16(float* c, const uint32_t* a, const uint32_t* b) {
    asm volatile(
        "mma.sync.aligned.m16n8k16.row.col.f32.f16.f16.f32 "
        "{%0,%1,%2,%3}, {%4,%5,%6,%7}, {%8,%9}, {%0,%1,%2,%3};"
        : "+f"(c[0]), "+f"(c[1]), "+f"(c[2]), "+f"(c[3])
        : "r"(a[0]), "r"(a[1]), "r"(a[2]), "r"(a[3]), "r"(b[0]), "r"(b[1]));
}

__device__ __forceinline__ void ldsm_x4(uint32_t* a, uint32_t saddr) {
    asm volatile("ldmatrix.sync.aligned.m8n8.x4.shared.b16 {%0,%1,%2,%3}, [%4];"
        : "=r"(a[0]), "=r"(a[1]), "=r"(a[2]), "=r"(a[3]) : "r"(saddr));
}

__device__ __forceinline__ float ssp(float z) {
    // shifted softplus, numerically stable
    return fmaxf(z, 0.f) + __logf(1.f + __expf(-fabsf(z))) - SHIFTC;
}

// ---------------- main fused kernel: one CTA (3 warps) per batch sample ----------------
// R10 post-mortem: A gathered from GMEM in fragment order costs 8 L1-wavefronts per
// LDG (8 rows x separate lines) and pins HBM at 3.4TB/s.  New path: each warp loads
// its 32 rows COALESCED (one LDG.128 per row = 4 wf for 512B), converts to fp16,
// stages in a swizzled SMEM tile, and builds fragments with ldmatrix.x4 (conflict-
// free).  Warp-private tile -> only __syncwarp, no CTA barrier.
__global__ void __launch_bounds__(96, 5)
atomwise_kernel(const float* __restrict__ rep,
                const int*   __restrict__ atomic_numbers,
                const float* __restrict__ atom_mask,
                const float* __restrict__ b1,
                const float* __restrict__ W2,
                const float* __restrict__ b2,
                const float* __restrict__ atomref,
                const float* __restrict__ mean,
                const float* __restrict__ stddev,
                float*       __restrict__ out) {
    __shared__ __align__(16) unsigned char smA[3][WTILE];
    __shared__ float red[4];

    const int tid  = threadIdx.x;
    const int w    = tid >> 5;          // warp 0..2
    const int lane = tid & 31;
    const int b    = blockIdx.x;

    const int qr = lane >> 2;           // 0..7 (row group)
    const int qc = lane & 3;            // 0..3 (col pair)
    const int r0 = w * 32 + qr;         // rows r0, r0+8 (m-tile 0); r0+16, r0+24 (m-tile 1)

    const float* xb = rep + (size_t)b * (NATOM * NIN);
    const uint32_t sbase = (uint32_t)__cvta_generic_to_shared(&smA[w][0]);

    // ---- fill phase: 32 coalesced row loads (LDG.128), cvt to fp16, swizzled STS.64 ----
    {
        const float4* rowsrc = reinterpret_cast<const float4*>(xb + (w * 32) * NIN);
        #pragma unroll
        for (int rr = 0; rr < 32; rr += 8) {
            float4 v[8];
            #pragma unroll
            for (int j = 0; j < 8; j++)
                v[j] = __ldg(rowsrc + (rr + j) * (NIN / 4) + lane);
            #pragma unroll
            for (int j = 0; j < 8; j++) {
                int r = rr + j;
                __half2 h0 = __floats2half2_rn(v[j].x, v[j].y);
                __half2 h1 = __floats2half2_rn(v[j].z, v[j].w);
                uint32_t u0 = *reinterpret_cast<uint32_t*>(&h0);
                uint32_t u1 = *reinterpret_cast<uint32_t*>(&h1);
                uint32_t off = (uint32_t)(r * ROWB + ((lane * 8) ^ (((r >> 3) & 1) << 4)));
                asm volatile("st.shared.v2.u32 [%0], {%1,%2};"
                             :: "r"(sbase + off), "r"(u0), "r"(u1));
            }
        }
    }
    __syncwarp();

    float acc[2][8][4];
    #pragma unroll
    for (int m = 0; m < 2; m++)
        #pragma unroll
        for (int nt = 0; nt < 8; nt++)
            #pragma unroll
            for (int r = 0; r < 4; r++) acc[m][nt][r] = 0.f;

    // ldmatrix lane addressing: lanes 0-7 rows 0-7 k-lo, 8-15 rows 8-15 k-lo,
    // 16-23 rows 0-7 k-hi, 24-31 rows 8-15 k-hi  (matches mma A reg order)
    const uint32_t rsel = lane & 15;
    const uint32_t csel = (uint32_t)(lane >> 4) * 16;   // byte offset of k-half

    #pragma unroll
    for (int kt = 0; kt < 8; kt++) {
        uint32_t a0[4], a1[4];
        {
            uint32_t r = rsel;                         // m-tile 0: rows 0..15
            uint32_t col = ((uint32_t)(kt * 32) + csel) ^ (((r >> 3) & 1) << 4);
            ldsm_x4(a0, sbase + r * ROWB + col);
        }
        {
            uint32_t r = 16 + rsel;                    // m-tile 1: rows 16..31
            uint32_t col = ((uint32_t)(kt * 32) + csel) ^ (((r >> 3) & 1) << 4);
            ldsm_x4(a1, sbase + r * ROWB + col);
        }

        #pragma unroll
        for (int nt = 0; nt < 8; nt++) {
            uint2 bb = __ldg(&g_wh[(nt * 8 + kt) * 32 + lane]);  // L1-hit after warmup
            mma_f16(acc[0][nt], a0, &bb.x);
            mma_f16(acc[1][nt], a1, &bb.x);
        }
    }

    // ---- epilogue: bias + ssp + W2 dot, quad shuffle-reduce ----
    float sum0 = 0.f, sum1 = 0.f, sum2 = 0.f, sum3 = 0.f;  // rows r0, r0+8, r0+16, r0+24
    const int tg2 = qc * 2;
    #pragma unroll
    for (int nt = 0; nt < 8; nt++) {
        int c0 = nt * 8 + tg2;
        float2 b1v = __ldg(reinterpret_cast<const float2*>(b1 + c0));
        float2 w2v = __ldg(reinterpret_cast<const float2*>(W2 + c0));
        sum0 = fmaf(ssp(acc[0][nt][0] + b1v.x), w2v.x, sum0);
        sum0 = fmaf(ssp(acc[0][nt][1] + b1v.y), w2v.y, sum0);
        sum1 = fmaf(ssp(acc[0][nt][2] + b1v.x), w2v.x, sum1);
        sum1 = fmaf(ssp(acc[0][nt][3] + b1v.y), w2v.y, sum1);
        sum2 = fmaf(ssp(acc[1][nt][0] + b1v.x), w2v.x, sum2);
        sum2 = fmaf(ssp(acc[1][nt][1] + b1v.y), w2v.y, sum2);
        sum3 = fmaf(ssp(acc[1][nt][2] + b1v.x), w2v.x, sum3);
        sum3 = fmaf(ssp(acc[1][nt][3] + b1v.y), w2v.y, sum3);
    }
    // reduce over the 4 lanes of each quad (cols)
    sum0 += __shfl_xor_sync(0xffffffffu, sum0, 1);
    sum0 += __shfl_xor_sync(0xffffffffu, sum0, 2);
    sum1 += __shfl_xor_sync(0xffffffffu, sum1, 1);
    sum1 += __shfl_xor_sync(0xffffffffu, sum1, 2);
    sum2 += __shfl_xor_sync(0xffffffffu, sum2, 1);
    sum2 += __shfl_xor_sync(0xffffffffu, sum2, 2);
    sum3 += __shfl_xor_sync(0xffffffffu, sum3, 1);
    sum3 += __shfl_xor_sync(0xffffffffu, sum3, 2);

    // per-row finish on quad leaders, then warp-sum (deterministic)
    float contrib = 0.f;
    if (qc == 0) {
        float scB2 = b2[0], scMean = mean[0], scStd = stddev[0];
        float s[4] = {sum0, sum1, sum2, sum3};
        float tot = 0.f;
        #pragma unroll
        for (int m = 0; m < 4; m++) {
            int row = r0 + m * 8;
            int g = b * NATOM + row;
            float v = (s[m] + scB2) * scStd + scMean;
            v += atomref[atomic_numbers[g]];
            v *= atom_mask[g];
            tot += v;
        }
        contrib = tot;
    }
    // nonzero only at lanes ≡ 0 (mod 4): stages 4, 8, 16 suffice
    contrib += __shfl_xor_sync(0xffffffffu, contrib, 4);
    contrib += __shfl_xor_sync(0xffffffffu, contrib, 8);
    contrib += __shfl_xor_sync(0xffffffffu, contrib, 16);

    if (lane == 0) red[w] = contrib;
    __syncthreads();
    if (tid == 0) out[b] = red[0] + red[1] + red[2];
}

// ---------------- host launch ----------------
extern "C" void kernel_launch(void* const* d_in, const int* in_sizes, int n_in,
                              void* d_out, int out_size) {
    const float* rep   = (const float*)d_in[0];
    const int*   zn    = (const int*)  d_in[1];
    const float* mask  = (const float*)d_in[2];
    const float* W1    = (const float*)d_in[3];
    const float* b1    = (const float*)d_in[4];
    const float* W2    = (const float*)d_in[5];
    const float* b2    = (const float*)d_in[6];
    const float* aref  = (const float*)d_in[7];
    const float* mean  = (const float*)d_in[8];
    const float* stdd  = (const float*)d_in[9];
    float* out = (float*)d_out;

    prep_w_kernel<<<32, 256>>>(W1);
    atomwise_kernel<<<BATCH, 96>>>(rep, zn, mask, b1, W2, b2, aref, mean, stdd, out);
}